// round 3
// baseline (speedup 1.0000x reference)
#include <cuda_runtime.h>
#include <cstdint>

// Problem constants
#define Bv   32
#define Tv   168
#define NHv  32
#define NMv  64
#define Ev   384
#define HGv  64
#define HLv  128
#define G4   512          // 4*HID_LSTM
#define FUT  24
#define GT   (Bv*Tv)      // 5376 graphs

// -------- scratch (static device arrays; no runtime allocation) --------
__device__ float d_gnnh[(size_t)NHv * GT * HGv];          // [s][g=b*T+t][k]   44 MB
__device__ float d_whhT[(size_t)NHv * HLv * G4];          // [s][k][j]          8 MB
__device__ float d_bsum[NHv * G4];                        // bih+bhh
__device__ float d_xproj[(size_t)NHv * 4 * Tv * G4 * 8];  // [(s*4+bg)][t][j][bi] 352 MB
__device__ float d_hfin[NHv * Bv * HLv];                  // [s][b][n]
__device__ int   d_edges[2 * Ev];                         // decoded edge list (int32)

typedef unsigned long long u64t;

__device__ __forceinline__ u64t pk2(float x, float y) {
    u64t r; asm("mov.b64 %0,{%1,%2};" : "=l"(r) : "f"(x), "f"(y)); return r;
}
__device__ __forceinline__ u64t fma2(u64t a, u64t b, u64t c) {
    u64t r; asm("fma.rn.f32x2 %0,%1,%2,%3;" : "=l"(r) : "l"(a), "l"(b), "l"(c)); return r;
}
__device__ __forceinline__ float sigf(float x) { return 1.0f / (1.0f + __expf(-x)); }
__device__ __forceinline__ float lrelu(float v) { return v > 0.0f ? v : 0.01f * v; }

// =====================================================================
// Kernel E: dtype-robust edge decode. edge_index is logically int64 in the
// reference, but JAX x64-off silently emits int32. Detect on device:
// among the first 2*Ev 32-bit words, odd indices are ~all zero iff int64
// (high halves of values < 96); for int32 they are values in [0,96).
// =====================================================================
__global__ void kE(const void* __restrict__ ei) {
    __shared__ int nz;
    const int* w = (const int*)ei;
    if (threadIdx.x == 0) nz = 0;
    __syncthreads();
    int cnt = 0;
    for (int i = threadIdx.x; i < 2 * Ev; i += blockDim.x)
        if ((i & 1) && w[i] == 0) cnt++;
    // warp-reduce then atomic
    for (int o = 16; o > 0; o >>= 1) cnt += __shfl_down_sync(0xffffffffu, cnt, o);
    if ((threadIdx.x & 31) == 0) atomicAdd(&nz, cnt);
    __syncthreads();
    bool is64 = (nz > 100);
    for (int i = threadIdx.x; i < 2 * Ev; i += blockDim.x)
        d_edges[i] = is64 ? (int)((const long long*)ei)[i] : w[i];
}

// =====================================================================
// Kernel A: GNN. One block per graph g. agg only for hydro dst (<32).
// gnnh[s][g][k] = lrelu(xh[s]*Wr[k] + agg[s]*Wl[k] + b[k])
// =====================================================================
__global__ void kA(const float* __restrict__ hyd, const float* __restrict__ met,
                   const float* __restrict__ Wr, const float* __restrict__ Wl,
                   const float* __restrict__ bg) {
    __shared__ float xh[NHv], xm[NMv], agg[NHv], wr[HGv], wl[HGv], bb[HGv];
    __shared__ short esrc[Ev], edst[Ev];
    int g = blockIdx.x;
    int tid = threadIdx.x;  // 128 threads

    if (tid < NHv) xh[tid] = hyd[(size_t)g * NHv + tid];
    if (tid >= 32 && tid < 96) xm[tid - 32] = met[(size_t)g * NMv + (tid - 32)];
    if (tid < HGv) { wr[tid] = Wr[tid]; wl[tid] = Wl[tid]; bb[tid] = bg[tid]; }
    for (int e = tid; e < Ev; e += 128) {
        esrc[e] = (short)d_edges[e];
        edst[e] = (short)d_edges[Ev + e];
    }
    __syncthreads();

    if (tid < NHv) {
        float s = 0.0f;
        for (int e = 0; e < Ev; e++) {
            if (edst[e] == tid) {
                int sr = esrc[e];
                s += (sr < NHv) ? xh[sr] : xm[sr - NHv];
            }
        }
        agg[tid] = s;
    }
    __syncthreads();

    for (int idx = tid; idx < NHv * HGv; idx += 128) {
        int s = idx >> 6, k = idx & 63;
        float v = xh[s] * wr[k] + agg[s] * wl[k] + bb[k];
        d_gnnh[((size_t)s * GT + g) * HGv + k] = lrelu(v);
    }
}

// =====================================================================
// Kernel W: transpose Whh -> WhhT[s][k][j]; bsum = bih+bhh
// grid (k=128, s=32), 512 threads (j)
// =====================================================================
__global__ void kW(const float* __restrict__ whh, const float* __restrict__ bih,
                   const float* __restrict__ bhh) {
    int k = blockIdx.x, s = blockIdx.y, j = threadIdx.x;
    d_whhT[((size_t)s * HLv + k) * G4 + j] =
        whh[(size_t)s * (G4 * HLv) + (size_t)j * HLv + k];
    if (k == 0) d_bsum[s * G4 + j] = bih[s * G4 + j] + bhh[s * G4 + j];
}

// =====================================================================
// Kernel B: input projection. grid (t=168, s=32), 512 threads (j).
// xproj[(s*4+bg)][t][j][bi] = sum_k gnnh[s][b*T+t][k]*Wih[s][j][k] + bsum[s][j]
// =====================================================================
__global__ void __launch_bounds__(512) kB(const float* __restrict__ wih) {
    int t = blockIdx.x, s = blockIdx.y;
    int j = threadIdx.x;
    __shared__ float hloc[64 * 36];  // [k][b], pad 36 for conflict-light stores

    {   // load + transpose: thread -> (b, 4 k's)
        int b = j >> 4, k4 = (j & 15) * 4;
        float4 hv = *reinterpret_cast<const float4*>(
            &d_gnnh[((size_t)s * GT + (size_t)b * Tv + t) * HGv + k4]);
        hloc[(k4 + 0) * 36 + b] = hv.x;
        hloc[(k4 + 1) * 36 + b] = hv.y;
        hloc[(k4 + 2) * 36 + b] = hv.z;
        hloc[(k4 + 3) * 36 + b] = hv.w;
    }
    __syncthreads();

    u64t acc[16];
    {
        float bias = d_bsum[s * G4 + j];
        u64t b2 = pk2(bias, bias);
        #pragma unroll
        for (int q = 0; q < 16; q++) acc[q] = b2;
    }

    const float* wrow = wih + (size_t)s * (G4 * HGv) + (size_t)j * HGv;
    for (int k4 = 0; k4 < 64; k4 += 4) {
        float4 w4 = *reinterpret_cast<const float4*>(wrow + k4);
        float wv[4] = {w4.x, w4.y, w4.z, w4.w};
        #pragma unroll
        for (int i = 0; i < 4; i++) {
            int k = k4 + i;
            u64t w2 = pk2(wv[i], wv[i]);
            const ulonglong2* hp = reinterpret_cast<const ulonglong2*>(&hloc[k * 36]);
            #pragma unroll
            for (int q2 = 0; q2 < 8; q2++) {
                ulonglong2 hh = hp[q2];
                acc[2 * q2 + 0] = fma2(hh.x, w2, acc[2 * q2 + 0]);
                acc[2 * q2 + 1] = fma2(hh.y, w2, acc[2 * q2 + 1]);
            }
        }
    }

    #pragma unroll
    for (int bg = 0; bg < 4; bg++) {
        float* base = &d_xproj[(((size_t)(s * 4 + bg) * Tv + t) * G4 + j) * 8];
        ulonglong2 v0; v0.x = acc[4 * bg + 0]; v0.y = acc[4 * bg + 1];
        ulonglong2 v1; v1.x = acc[4 * bg + 2]; v1.y = acc[4 * bg + 3];
        reinterpret_cast<ulonglong2*>(base)[0] = v0;
        reinterpret_cast<ulonglong2*>(base)[1] = v1;
    }
}

// =====================================================================
// Kernel C: recurrence. 128 blocks = (s, bg), 512 threads (gate j).
// smem: WhhT k<64 (128KB) + hbuf[128][8] + gsm[512][8]. k>=64 streamed from L2.
// =====================================================================
#define SMEM_C (64 * 512 * 4 + 128 * 8 * 4 + 512 * 8 * 4)

extern __shared__ float smc[];

__global__ void __launch_bounds__(512) kC() {
    int blk = blockIdx.x;
    int s = blk >> 2, bg = blk & 3;
    int j = threadIdx.x;

    float* wlo  = smc;                 // [64][512]
    float* hbuf = smc + 64 * 512;      // [128][8]
    float* gsm  = hbuf + 128 * 8;      // [512][8]

    const float* whhTs = d_whhT + (size_t)s * (HLv * G4);
    // resident half: k in [0,64)
    for (int k = 0; k < 64; k++)
        wlo[k * 512 + j] = whhTs[(size_t)k * G4 + j];
    hbuf[j] = 0.0f;
    hbuf[j + 512] = 0.0f;

    float c[8];
    #pragma unroll
    for (int bi = 0; bi < 8; bi++) c[bi] = 0.0f;

    const float* xp = d_xproj + (size_t)(s * 4 + bg) * Tv * (G4 * 8) + (size_t)j * 8;
    ulonglong2 xa = reinterpret_cast<const ulonglong2*>(xp)[0];
    ulonglong2 xb = reinterpret_cast<const ulonglong2*>(xp)[1];
    __syncthreads();

    for (int t = 0; t < Tv; t++) {
        u64t acc[4] = {xa.x, xa.y, xb.x, xb.y};
        if (t < Tv - 1) {  // prefetch next step's input projection
            const float* xn = xp + (size_t)(t + 1) * (G4 * 8);
            xa = reinterpret_cast<const ulonglong2*>(xn)[0];
            xb = reinterpret_cast<const ulonglong2*>(xn)[1];
        }

        // phase 1: smem-resident weights, k in [0,64)
        #pragma unroll 8
        for (int k = 0; k < 64; k++) {
            float w = wlo[k * 512 + j];
            u64t w2 = pk2(w, w);
            const ulonglong2* hp = reinterpret_cast<const ulonglong2*>(&hbuf[k * 8]);
            ulonglong2 h0 = hp[0], h1 = hp[1];
            acc[0] = fma2(h0.x, w2, acc[0]);
            acc[1] = fma2(h0.y, w2, acc[1]);
            acc[2] = fma2(h1.x, w2, acc[2]);
            acc[3] = fma2(h1.y, w2, acc[3]);
        }

        // phase 2: L2-streamed weights, k in [64,128) with reg prefetch ring
        float wq[8];
        #pragma unroll
        for (int i = 0; i < 8; i++) wq[i] = __ldg(&whhTs[(size_t)(64 + i) * G4 + j]);
        for (int kb = 64; kb < 128; kb += 8) {
            #pragma unroll
            for (int i = 0; i < 8; i++) {
                int k = kb + i;
                float w = wq[i];
                if (kb + 8 < 128) wq[i] = __ldg(&whhTs[(size_t)(k + 8) * G4 + j]);
                u64t w2 = pk2(w, w);
                const ulonglong2* hp = reinterpret_cast<const ulonglong2*>(&hbuf[k * 8]);
                ulonglong2 h0 = hp[0], h1 = hp[1];
                acc[0] = fma2(h0.x, w2, acc[0]);
                acc[1] = fma2(h0.y, w2, acc[1]);
                acc[2] = fma2(h1.x, w2, acc[2]);
                acc[3] = fma2(h1.y, w2, acc[3]);
            }
        }

        ulonglong2 g0; g0.x = acc[0]; g0.y = acc[1];
        ulonglong2 g1; g1.x = acc[2]; g1.y = acc[3];
        reinterpret_cast<ulonglong2*>(&gsm[j * 8])[0] = g0;
        reinterpret_cast<ulonglong2*>(&gsm[j * 8])[1] = g1;
        __syncthreads();

        if (j < HLv) {  // cell update: thread j = hidden unit n
            float iv[8], fv[8], gv[8], ov[8], hv[8];
            *reinterpret_cast<float4*>(&iv[0]) = *reinterpret_cast<float4*>(&gsm[j * 8]);
            *reinterpret_cast<float4*>(&iv[4]) = *reinterpret_cast<float4*>(&gsm[j * 8 + 4]);
            *reinterpret_cast<float4*>(&fv[0]) = *reinterpret_cast<float4*>(&gsm[(j + 128) * 8]);
            *reinterpret_cast<float4*>(&fv[4]) = *reinterpret_cast<float4*>(&gsm[(j + 128) * 8 + 4]);
            *reinterpret_cast<float4*>(&gv[0]) = *reinterpret_cast<float4*>(&gsm[(j + 256) * 8]);
            *reinterpret_cast<float4*>(&gv[4]) = *reinterpret_cast<float4*>(&gsm[(j + 256) * 8 + 4]);
            *reinterpret_cast<float4*>(&ov[0]) = *reinterpret_cast<float4*>(&gsm[(j + 384) * 8]);
            *reinterpret_cast<float4*>(&ov[4]) = *reinterpret_cast<float4*>(&gsm[(j + 384) * 8 + 4]);
            #pragma unroll
            for (int bi = 0; bi < 8; bi++) {
                float cc = sigf(fv[bi]) * c[bi] + sigf(iv[bi]) * tanhf(gv[bi]);
                c[bi] = cc;
                hv[bi] = sigf(ov[bi]) * tanhf(cc);
            }
            *reinterpret_cast<float4*>(&hbuf[j * 8])     = *reinterpret_cast<float4*>(&hv[0]);
            *reinterpret_cast<float4*>(&hbuf[j * 8 + 4]) = *reinterpret_cast<float4*>(&hv[4]);
        }
        __syncthreads();
    }

    if (j < HLv) {
        #pragma unroll
        for (int bi = 0; bi < 8; bi++) {
            int b = bg * 8 + bi;
            d_hfin[((size_t)s * Bv + b) * HLv + j] = hbuf[j * 8 + bi];
        }
    }
}

// =====================================================================
// Kernel D: final linear + lrelu. grid 1024 = s*32+b, 32 threads.
// out[b][s][f] = lrelu(hfin[s][b] . W_lin[f] + b_lin[f])
// =====================================================================
__global__ void kD(const float* __restrict__ wlin, const float* __restrict__ blin,
                   float* __restrict__ out) {
    int s = blockIdx.x >> 5, b = blockIdx.x & 31;
    int f = threadIdx.x;
    __shared__ float hs[HLv];
    for (int i = threadIdx.x; i < HLv; i += 32)
        hs[i] = d_hfin[((size_t)s * Bv + b) * HLv + i];
    __syncthreads();
    if (f < FUT) {
        float a = blin[f];
        #pragma unroll 8
        for (int k = 0; k < HLv; k++) a += hs[k] * wlin[f * HLv + k];
        out[((size_t)b * NHv + s) * FUT + f] = lrelu(a);
    }
}

// =====================================================================
extern "C" void kernel_launch(void* const* d_in, const int* in_sizes, int n_in,
                              void* d_out, int out_size) {
    // size-robust assignment where sizes disambiguate
    const float* meteo = (const float*)d_in[0];
    const float* hydro = (const float*)d_in[1];
    if (in_sizes[0] == Bv * Tv * NHv) {  // inputs swapped vs expectation
        hydro = (const float*)d_in[0];
        meteo = (const float*)d_in[1];
    }
    const void*  ei    = d_in[2];
    const float* Wr    = (const float*)d_in[3];
    const float* Wl    = (const float*)d_in[4];
    const float* bgnn  = (const float*)d_in[5];
    const float* Wih   = (const float*)d_in[6];
    const float* Whh   = (const float*)d_in[7];
    if (in_sizes[6] == NHv * G4 * HLv) {  // swapped
        Whh = (const float*)d_in[6];
        Wih = (const float*)d_in[7];
    }
    const float* bih   = (const float*)d_in[8];
    const float* bhh   = (const float*)d_in[9];
    const float* Wlin  = (const float*)d_in[10];
    const float* blin  = (const float*)d_in[11];
    float* out = (float*)d_out;

    cudaFuncSetAttribute(kC, cudaFuncAttributeMaxDynamicSharedMemorySize, SMEM_C);

    kE<<<1, 256>>>(ei);
    kA<<<GT, 128>>>(hydro, meteo, Wr, Wl, bgnn);
    kW<<<dim3(HLv, NHv), 512>>>(Whh, bih, bhh);
    kB<<<dim3(Tv, NHv), 512>>>(Wih);
    kC<<<128, 512, SMEM_C>>>();
    kD<<<NHv * Bv, 32>>>(Wlin, blin, out);
}

// round 5
// speedup vs baseline: 1.4016x; 1.4016x over previous
#include <cuda_runtime.h>
#include <cstdint>

#define Bv   32
#define Tv   168
#define NHv  32
#define NMv  64
#define Ev   384
#define HGv  64
#define HLv  128
#define G4   512
#define FUT  24
#define GT   (Bv*Tv)

#define RES   100        // Whh rows resident in smem (kC)
#define NSTRM 28         // Whh rows resident in registers (kC)

// -------- scratch --------
__device__ float d_gnnh[(size_t)NHv * Tv * Bv * HGv];     // [s][t][b][k]
__device__ float d_whhT[(size_t)NHv * HLv * G4];          // [s][k][j]
__device__ float d_wihT[(size_t)NHv * HGv * G4];          // [s][k][j]
__device__ float d_bsum[NHv * G4];
__device__ float d_xproj[(size_t)NHv * 4 * Tv * G4 * 8];  // [(s*4+bg)][t][j][bi]
__device__ float d_hfin[NHv * Bv * HLv];                  // [s][b][n]
__device__ int   d_edges[2 * Ev];

typedef unsigned long long u64t;

__device__ __forceinline__ u64t pk2(float x, float y) {
    u64t r; asm("mov.b64 %0,{%1,%2};" : "=l"(r) : "f"(x), "f"(y)); return r;
}
__device__ __forceinline__ u64t fma2(u64t a, u64t b, u64t c) {
    u64t r; asm("fma.rn.f32x2 %0,%1,%2,%3;" : "=l"(r) : "l"(a), "l"(b), "l"(c)); return r;
}
__device__ __forceinline__ float sigf(float x) {
    return __fdividef(1.0f, 1.0f + __expf(-x));
}
__device__ __forceinline__ float tanhfast(float x) {
    // tanh(x) = 1 - 2/(e^{2x}+1); saturates correctly at +/-1
    return 1.0f - 2.0f * __fdividef(1.0f, __expf(2.0f * x) + 1.0f);
}
__device__ __forceinline__ float lrelu(float v) { return v > 0.0f ? v : 0.01f * v; }

// =====================================================================
// kE: dtype-robust edge decode (int64 vs silently-int32 edge_index)
// =====================================================================
__global__ void kE(const void* __restrict__ ei) {
    __shared__ int nz;
    const int* w = (const int*)ei;
    if (threadIdx.x == 0) nz = 0;
    __syncthreads();
    int cnt = 0;
    for (int i = threadIdx.x; i < 2 * Ev; i += blockDim.x)
        if ((i & 1) && w[i] == 0) cnt++;
    for (int o = 16; o > 0; o >>= 1) cnt += __shfl_down_sync(0xffffffffu, cnt, o);
    if ((threadIdx.x & 31) == 0) atomicAdd(&nz, cnt);
    __syncthreads();
    bool is64 = (nz > 100);
    for (int i = threadIdx.x; i < 2 * Ev; i += blockDim.x)
        d_edges[i] = is64 ? (int)((const long long*)ei)[i] : w[i];
}

// =====================================================================
// kA: GNN per graph g = b*T + t. Output layout [s][t][b][k].
// =====================================================================
__global__ void kA(const float* __restrict__ hyd, const float* __restrict__ met,
                   const float* __restrict__ Wr, const float* __restrict__ Wl,
                   const float* __restrict__ bg) {
    __shared__ float xh[NHv], xm[NMv], agg[NHv], wr[HGv], wl[HGv], bb[HGv];
    __shared__ short esrc[Ev], edst[Ev];
    int g = blockIdx.x;
    int t = g % Tv, b = g / Tv;
    int tid = threadIdx.x;

    if (tid < NHv) xh[tid] = hyd[(size_t)g * NHv + tid];
    if (tid >= 32 && tid < 96) xm[tid - 32] = met[(size_t)g * NMv + (tid - 32)];
    if (tid < HGv) { wr[tid] = Wr[tid]; wl[tid] = Wl[tid]; bb[tid] = bg[tid]; }
    for (int e = tid; e < Ev; e += 128) {
        esrc[e] = (short)d_edges[e];
        edst[e] = (short)d_edges[Ev + e];
    }
    __syncthreads();

    if (tid < NHv) {
        float s = 0.0f;
        for (int e = 0; e < Ev; e++) {
            if (edst[e] == tid) {
                int sr = esrc[e];
                s += (sr < NHv) ? xh[sr] : xm[sr - NHv];
            }
        }
        agg[tid] = s;
    }
    __syncthreads();

    for (int idx = tid; idx < NHv * HGv; idx += 128) {
        int s = idx >> 6, k = idx & 63;
        float v = xh[s] * wr[k] + agg[s] * wl[k] + bb[k];
        d_gnnh[(((size_t)s * Tv + t) * Bv + b) * HGv + k] = lrelu(v);
    }
}

// =====================================================================
// kW: transposes whh -> whhT[s][k][j], wih -> wihT[s][k][j]; bsum
// grid (k=128, s=32), 512 threads (j)
// =====================================================================
__global__ void kW(const float* __restrict__ whh, const float* __restrict__ wih,
                   const float* __restrict__ bih, const float* __restrict__ bhh) {
    int k = blockIdx.x, s = blockIdx.y, j = threadIdx.x;
    d_whhT[((size_t)s * HLv + k) * G4 + j] =
        whh[(size_t)s * (G4 * HLv) + (size_t)j * HLv + k];
    if (k < HGv)
        d_wihT[((size_t)s * HGv + k) * G4 + j] =
            wih[(size_t)s * (G4 * HGv) + (size_t)j * HGv + k];
    if (k == 0) d_bsum[s * G4 + j] = bih[s * G4 + j] + bhh[s * G4 + j];
}

// =====================================================================
// kB: input projection. grid (t, s, z=bhalf), 256 threads.
// Thread jj handles j = 2jj, 2jj+1 over 16 batches (z half).
// =====================================================================
__global__ void __launch_bounds__(256) kB() {
    int t = blockIdx.x, s = blockIdx.y, z = blockIdx.z;
    int jj = threadIdx.x;
    __shared__ float hloc[64 * 20];  // [k][b16], pad 20

    {   // fully coalesced fill + smem transpose
        const float* src = &d_gnnh[(((size_t)s * Tv + t) * Bv + z * 16) * HGv];
        float4 v = *reinterpret_cast<const float4*>(src + jj * 4);
        int bl = jj >> 4, k0 = (jj & 15) * 4;
        hloc[(k0 + 0) * 20 + bl] = v.x;
        hloc[(k0 + 1) * 20 + bl] = v.y;
        hloc[(k0 + 2) * 20 + bl] = v.z;
        hloc[(k0 + 3) * 20 + bl] = v.w;
    }
    __syncthreads();

    int j0 = jj * 2;
    u64t acc[2][8];
    {
        float2 bb = *reinterpret_cast<const float2*>(&d_bsum[s * G4 + j0]);
        u64t b0 = pk2(bb.x, bb.x), b1 = pk2(bb.y, bb.y);
        #pragma unroll
        for (int p = 0; p < 8; p++) { acc[0][p] = b0; acc[1][p] = b1; }
    }

    const float* wT = d_wihT + (size_t)s * (HGv * G4);
    #pragma unroll 4
    for (int k = 0; k < 64; k++) {
        float2 w = *reinterpret_cast<const float2*>(&wT[k * G4 + j0]);  // coalesced
        u64t w0 = pk2(w.x, w.x), w1 = pk2(w.y, w.y);
        const ulonglong2* hp = reinterpret_cast<const ulonglong2*>(&hloc[k * 20]);
        #pragma unroll
        for (int q = 0; q < 4; q++) {
            ulonglong2 hh = hp[q];
            acc[0][2 * q + 0] = fma2(hh.x, w0, acc[0][2 * q + 0]);
            acc[0][2 * q + 1] = fma2(hh.y, w0, acc[0][2 * q + 1]);
            acc[1][2 * q + 0] = fma2(hh.x, w1, acc[1][2 * q + 0]);
            acc[1][2 * q + 1] = fma2(hh.y, w1, acc[1][2 * q + 1]);
        }
    }

    #pragma unroll
    for (int jsel = 0; jsel < 2; jsel++) {
        #pragma unroll
        for (int bgl = 0; bgl < 2; bgl++) {
            float* base = &d_xproj[(((size_t)(s * 4 + z * 2 + bgl) * Tv + t) * G4
                                    + (j0 + jsel)) * 8];
            ulonglong2 v0, v1;
            v0.x = acc[jsel][4 * bgl + 0]; v0.y = acc[jsel][4 * bgl + 1];
            v1.x = acc[jsel][4 * bgl + 2]; v1.y = acc[jsel][4 * bgl + 3];
            reinterpret_cast<ulonglong2*>(base)[0] = v0;
            reinterpret_cast<ulonglong2*>(base)[1] = v1;
        }
    }
}

// =====================================================================
// kC: recurrence. 128 blocks = (s, bg of 8 batches), 512 threads.
// Whh: 100 rows in smem, 28 rows held in registers for all 168 steps.
// =====================================================================
#define SMEM_C (RES * G4 * 4 + 1024 * 4 + G4 * 8 * 4)  // 225280 B

extern __shared__ float smc[];

__global__ void __launch_bounds__(512) kC() {
    int blk = blockIdx.x;
    int s = blk >> 2, bg = blk & 3;
    int j = threadIdx.x;

    float* wlo  = smc;               // [RES][512]
    float* hbuf = smc + RES * G4;    // [128n * 8bi]
    float* gsm  = hbuf + 1024;       // [512j * 8bi]

    const float* whhTs = d_whhT + (size_t)s * (HLv * G4);
    for (int idx = j; idx < RES * G4; idx += 512) wlo[idx] = whhTs[idx];  // coalesced
    hbuf[j] = 0.0f;
    hbuf[j + 512] = 0.0f;

    float wreg[NSTRM];                 // loop-invariant: stays in registers
    #pragma unroll
    for (int i = 0; i < NSTRM; i++)
        wreg[i] = whhTs[(size_t)(RES + i) * G4 + j];

    float c0 = 0.0f, c1 = 0.0f;        // cell state for items j and j+512

    const float* xp = d_xproj + (size_t)(s * 4 + bg) * Tv * (G4 * 8) + (size_t)j * 8;
    ulonglong2 xa = reinterpret_cast<const ulonglong2*>(xp)[0];
    ulonglong2 xb = reinterpret_cast<const ulonglong2*>(xp)[1];
    __syncthreads();

    for (int t = 0; t < Tv; t++) {
        u64t acc[4] = {xa.x, xa.y, xb.x, xb.y};
        if (t < Tv - 1) {
            const float* xn = xp + (size_t)(t + 1) * (G4 * 8);
            xa = reinterpret_cast<const ulonglong2*>(xn)[0];
            xb = reinterpret_cast<const ulonglong2*>(xn)[1];
        }

        #pragma unroll 4
        for (int k = 0; k < RES; k++) {
            float w = wlo[k * G4 + j];
            u64t w2 = pk2(w, w);
            const ulonglong2* hp = reinterpret_cast<const ulonglong2*>(&hbuf[k * 8]);
            ulonglong2 h0 = hp[0], h1 = hp[1];
            acc[0] = fma2(h0.x, w2, acc[0]);
            acc[1] = fma2(h0.y, w2, acc[1]);
            acc[2] = fma2(h1.x, w2, acc[2]);
            acc[3] = fma2(h1.y, w2, acc[3]);
        }
        #pragma unroll
        for (int i = 0; i < NSTRM; i++) {
            u64t w2 = pk2(wreg[i], wreg[i]);
            const ulonglong2* hp =
                reinterpret_cast<const ulonglong2*>(&hbuf[(RES + i) * 8]);
            ulonglong2 h0 = hp[0], h1 = hp[1];
            acc[0] = fma2(h0.x, w2, acc[0]);
            acc[1] = fma2(h0.y, w2, acc[1]);
            acc[2] = fma2(h1.x, w2, acc[2]);
            acc[3] = fma2(h1.y, w2, acc[3]);
        }

        ulonglong2 g0; g0.x = acc[0]; g0.y = acc[1];
        ulonglong2 g1; g1.x = acc[2]; g1.y = acc[3];
        reinterpret_cast<ulonglong2*>(&gsm[j * 8])[0] = g0;
        reinterpret_cast<ulonglong2*>(&gsm[j * 8])[1] = g1;
        __syncthreads();

        // gate update: all 512 threads, items m0=j, m1=j+512 (m = n*8+bi)
        {
            float iv0 = gsm[j],        fv0 = gsm[j + 1024];
            float gv0 = gsm[j + 2048], ov0 = gsm[j + 3072];
            float iv1 = gsm[j + 512],        fv1 = gsm[j + 512 + 1024];
            float gv1 = gsm[j + 512 + 2048], ov1 = gsm[j + 512 + 3072];
            c0 = sigf(fv0) * c0 + sigf(iv0) * tanhfast(gv0);
            c1 = sigf(fv1) * c1 + sigf(iv1) * tanhfast(gv1);
            float h0v = sigf(ov0) * tanhfast(c0);
            float h1v = sigf(ov1) * tanhfast(c1);
            hbuf[j]       = h0v;
            hbuf[j + 512] = h1v;
        }
        __syncthreads();
    }

    {
        int n0 = j >> 3, bi0 = j & 7;
        d_hfin[((size_t)s * Bv + (bg * 8 + bi0)) * HLv + n0] = hbuf[j];
        int m1 = j + 512;
        int n1 = m1 >> 3, bi1 = m1 & 7;
        d_hfin[((size_t)s * Bv + (bg * 8 + bi1)) * HLv + n1] = hbuf[m1];
    }
}

// =====================================================================
// kD: final linear + lrelu
// =====================================================================
__global__ void kD(const float* __restrict__ wlin, const float* __restrict__ blin,
                   float* __restrict__ out) {
    int s = blockIdx.x >> 5, b = blockIdx.x & 31;
    int f = threadIdx.x;
    __shared__ float hs[HLv];
    for (int i = threadIdx.x; i < HLv; i += 32)
        hs[i] = d_hfin[((size_t)s * Bv + b) * HLv + i];
    __syncthreads();
    if (f < FUT) {
        float a = blin[f];
        #pragma unroll 8
        for (int k = 0; k < HLv; k++) a += hs[k] * wlin[f * HLv + k];
        out[((size_t)b * NHv + s) * FUT + f] = lrelu(a);
    }
}

// =====================================================================
extern "C" void kernel_launch(void* const* d_in, const int* in_sizes, int n_in,
                              void* d_out, int out_size) {
    const float* meteo = (const float*)d_in[0];
    const float* hydro = (const float*)d_in[1];
    if (in_sizes[0] == Bv * Tv * NHv) {
        hydro = (const float*)d_in[0];
        meteo = (const float*)d_in[1];
    }
    const void*  ei    = d_in[2];
    const float* Wr    = (const float*)d_in[3];
    const float* Wl    = (const float*)d_in[4];
    const float* bgnn  = (const float*)d_in[5];
    const float* Wih   = (const float*)d_in[6];
    const float* Whh   = (const float*)d_in[7];
    if (in_sizes[6] == NHv * G4 * HLv) {
        Whh = (const float*)d_in[6];
        Wih = (const float*)d_in[7];
    }
    const float* bih   = (const float*)d_in[8];
    const float* bhh   = (const float*)d_in[9];
    const float* Wlin  = (const float*)d_in[10];
    const float* blin  = (const float*)d_in[11];
    float* out = (float*)d_out;

    cudaFuncSetAttribute(kC, cudaFuncAttributeMaxDynamicSharedMemorySize, SMEM_C);

    kE<<<1, 256>>>(ei);
    kA<<<GT, 128>>>(hydro, meteo, Wr, Wl, bgnn);
    kW<<<dim3(HLv, NHv), 512>>>(Whh, Wih, bih, bhh);
    kB<<<dim3(Tv, NHv, 2), 256>>>();
    kC<<<128, 512, SMEM_C>>>();
    kD<<<NHv * Bv, 32>>>(Wlin, blin, out);
}

// round 7
// speedup vs baseline: 1.6038x; 1.1442x over previous
#include <cuda_runtime.h>
#include <cstdint>

#define Bv   32
#define Tv   168
#define NHv  32
#define NMv  64
#define Ev   384
#define HGv  64
#define HLv  128
#define G4   512
#define FUT  24
#define GT   (Bv*Tv)

#define RES   104        // Whh rows resident in smem (kC)
#define NREG  24         // Whh rows resident in registers (kC)

// -------- scratch --------
__device__ float d_gnnh[(size_t)NHv * Tv * Bv * HGv];     // [s][t][b][k]
__device__ float d_whhT[(size_t)NHv * HLv * G4];          // [s][k][j]
__device__ float d_wihT[(size_t)NHv * HGv * G4];          // [s][k][j]
__device__ float d_bsum[NHv * G4];
__device__ float d_xproj[(size_t)NHv * 4 * Tv * G4 * 8];  // [(s*4+bg)][t][j][bi]
__device__ float d_hfin[NHv * Bv * HLv];                  // [s][b][n]
__device__ int   d_edges[2 * Ev];

typedef unsigned long long u64t;

__device__ __forceinline__ u64t pk2(float x, float y) {
    u64t r; asm("mov.b64 %0,{%1,%2};" : "=l"(r) : "f"(x), "f"(y)); return r;
}
__device__ __forceinline__ float2 up2(u64t v) {
    float2 f; asm("mov.b64 {%0,%1},%2;" : "=f"(f.x), "=f"(f.y) : "l"(v)); return f;
}
__device__ __forceinline__ u64t fma2(u64t a, u64t b, u64t c) {
    u64t r; asm("fma.rn.f32x2 %0,%1,%2,%3;" : "=l"(r) : "l"(a), "l"(b), "l"(c)); return r;
}
__device__ __forceinline__ float sigf(float x) {
    return __fdividef(1.0f, 1.0f + __expf(-x));
}
__device__ __forceinline__ float tanhfast(float x) {
    return 1.0f - 2.0f * __fdividef(1.0f, __expf(2.0f * x) + 1.0f);
}
__device__ __forceinline__ float lrelu(float v) { return v > 0.0f ? v : 0.01f * v; }

// =====================================================================
// kE: dtype-robust edge decode (int64 vs silently-int32 edge_index)
// =====================================================================
__global__ void kE(const void* __restrict__ ei) {
    __shared__ int nz;
    const int* w = (const int*)ei;
    if (threadIdx.x == 0) nz = 0;
    __syncthreads();
    int cnt = 0;
    for (int i = threadIdx.x; i < 2 * Ev; i += blockDim.x)
        if ((i & 1) && w[i] == 0) cnt++;
    for (int o = 16; o > 0; o >>= 1) cnt += __shfl_down_sync(0xffffffffu, cnt, o);
    if ((threadIdx.x & 31) == 0) atomicAdd(&nz, cnt);
    __syncthreads();
    bool is64 = (nz > 100);
    for (int i = threadIdx.x; i < 2 * Ev; i += blockDim.x)
        d_edges[i] = is64 ? (int)((const long long*)ei)[i] : w[i];
}

// =====================================================================
// kA: GNN per graph g = b*Tv + t. Output [s][t][b][k]. smem atomics for agg.
// =====================================================================
__global__ void __launch_bounds__(128) kA(
        const float* __restrict__ hyd, const float* __restrict__ met,
        const float* __restrict__ Wr, const float* __restrict__ Wl,
        const float* __restrict__ bg) {
    __shared__ float xv[96], agg[NHv], wr[HGv], wl[HGv], bb[HGv];
    int g = blockIdx.x;
    int t = g % Tv, b = g / Tv;
    int tid = threadIdx.x;

    if (tid < NHv) { xv[tid] = hyd[(size_t)g * NHv + tid]; agg[tid] = 0.0f; }
    if (tid >= 32 && tid < 96) xv[tid] = met[(size_t)g * NMv + (tid - 32)];
    if (tid < HGv) { wr[tid] = Wr[tid]; wl[tid] = Wl[tid]; bb[tid] = bg[tid]; }
    __syncthreads();

    #pragma unroll
    for (int r = 0; r < 3; r++) {
        int e = tid + r * 128;
        int dn = d_edges[Ev + e];
        if (dn < NHv) atomicAdd(&agg[dn], xv[d_edges[e]]);
    }
    __syncthreads();

    #pragma unroll
    for (int i = 0; i < 16; i++) {
        int idx = tid + i * 128;
        int s = idx >> 6, k = idx & 63;
        float v = xv[s] * wr[k] + agg[s] * wl[k] + bb[k];
        d_gnnh[(((size_t)s * Tv + t) * Bv + b) * HGv + k] = lrelu(v);
    }
}

// =====================================================================
// kT: tiled per-station transpose [s][J][K] -> [s][K][J]. which: 0=whh,1=wih
// grid (K/32, J/32, s), block (32, 8)
// =====================================================================
__global__ void kT(const float* __restrict__ src, int J, int K, int which) {
    __shared__ float tile[32][33];
    int s = blockIdx.z;
    int k0 = blockIdx.x * 32, j0 = blockIdx.y * 32;
    int tx = threadIdx.x, ty = threadIdx.y;
    const float* S = src + (size_t)s * J * K;
    float* D = (which == 0 ? d_whhT : d_wihT) + (size_t)s * J * K;
    #pragma unroll
    for (int dy = 0; dy < 32; dy += 8)
        tile[ty + dy][tx] = S[(size_t)(j0 + ty + dy) * K + (k0 + tx)];
    __syncthreads();
    #pragma unroll
    for (int dy = 0; dy < 32; dy += 8)
        D[(size_t)(k0 + ty + dy) * J + (j0 + tx)] = tile[tx][ty + dy];
}

__global__ void kBias(const float* __restrict__ bih, const float* __restrict__ bhh) {
    int s = blockIdx.x, j = threadIdx.x;
    d_bsum[s * G4 + j] = bih[s * G4 + j] + bhh[s * G4 + j];
}

// =====================================================================
// kB: input projection. grid (t, s, z), 128 threads; thread jj: 4 j's, 16 b.
// =====================================================================
__global__ void __launch_bounds__(128) kB() {
    int t = blockIdx.x, s = blockIdx.y, z = blockIdx.z;
    int jj = threadIdx.x;
    int j0 = jj * 4;
    __shared__ float hloc[64 * 20];  // [k][b16], pad to 20 (16B-aligned rows)

    {   // coalesced fill + transpose: 1024 floats = 256 float4, 2 per thread
        const float* src = &d_gnnh[(((size_t)s * Tv + t) * Bv + z * 16) * HGv];
        #pragma unroll
        for (int r = 0; r < 2; r++) {
            int id = jj + r * 128;
            float4 v = reinterpret_cast<const float4*>(src)[id];
            int b = id >> 4, k0 = (id & 15) * 4;
            hloc[(k0 + 0) * 20 + b] = v.x;
            hloc[(k0 + 1) * 20 + b] = v.y;
            hloc[(k0 + 2) * 20 + b] = v.z;
            hloc[(k0 + 3) * 20 + b] = v.w;
        }
    }
    __syncthreads();

    u64t acc[4][8];
    {
        float4 bb = *reinterpret_cast<const float4*>(&d_bsum[s * G4 + j0]);
        float bv[4] = {bb.x, bb.y, bb.z, bb.w};
        #pragma unroll
        for (int jl = 0; jl < 4; jl++) {
            u64t b2 = pk2(bv[jl], bv[jl]);
            #pragma unroll
            for (int q = 0; q < 8; q++) acc[jl][q] = b2;
        }
    }

    const float* wT = d_wihT + (size_t)s * (HGv * G4);
    #pragma unroll 2
    for (int k = 0; k < 64; k++) {
        float4 w = *reinterpret_cast<const float4*>(&wT[k * G4 + j0]);
        float wv[4] = {w.x, w.y, w.z, w.w};
        const ulonglong2* hp = reinterpret_cast<const ulonglong2*>(&hloc[k * 20]);
        ulonglong2 h0 = hp[0], h1 = hp[1], h2 = hp[2], h3 = hp[3];
        #pragma unroll
        for (int jl = 0; jl < 4; jl++) {
            u64t W = pk2(wv[jl], wv[jl]);
            acc[jl][0] = fma2(h0.x, W, acc[jl][0]);
            acc[jl][1] = fma2(h0.y, W, acc[jl][1]);
            acc[jl][2] = fma2(h1.x, W, acc[jl][2]);
            acc[jl][3] = fma2(h1.y, W, acc[jl][3]);
            acc[jl][4] = fma2(h2.x, W, acc[jl][4]);
            acc[jl][5] = fma2(h2.y, W, acc[jl][5]);
            acc[jl][6] = fma2(h3.x, W, acc[jl][6]);
            acc[jl][7] = fma2(h3.y, W, acc[jl][7]);
        }
    }

    #pragma unroll
    for (int jl = 0; jl < 4; jl++) {
        #pragma unroll
        for (int half = 0; half < 2; half++) {
            float* base = &d_xproj[(((size_t)(s * 4 + z * 2 + half) * Tv + t) * G4
                                    + (j0 + jl)) * 8];
            ulonglong2 v0, v1;
            v0.x = acc[jl][half * 4 + 0]; v0.y = acc[jl][half * 4 + 1];
            v1.x = acc[jl][half * 4 + 2]; v1.y = acc[jl][half * 4 + 3];
            reinterpret_cast<ulonglong2*>(base)[0] = v0;
            reinterpret_cast<ulonglong2*>(base)[1] = v1;
        }
    }
}

// =====================================================================
// kC: recurrence. 128 blocks = (s, bg), 128 threads.
// Thread jj owns gates {jj, jj+128, jj+256, jj+384} = i,f,g,o for unit n=jj,
// 8 batches -> gate update is thread-local. Double-buffered h, 1 sync/step.
// Whh: RES rows in smem, NREG rows in registers.
// =====================================================================
#define SMEM_C (RES * G4 * 4 + 2 * 1024 * 4)

extern __shared__ float smc[];

__global__ void __launch_bounds__(128) kC() {
    int blk = blockIdx.x;
    int s = blk >> 2, bg = blk & 3;
    int jj = threadIdx.x;

    float* wlo = smc;                   // [RES][512]
    float* hb0 = smc + RES * G4;        // [128][8] x2 (double buffer)
    float* hb1 = hb0 + 1024;

    const float* whhTs = d_whhT + (size_t)s * (HLv * G4);
    for (int idx = jj; idx < RES * G4 / 4; idx += 128)
        reinterpret_cast<float4*>(wlo)[idx] =
            reinterpret_cast<const float4*>(whhTs)[idx];
    #pragma unroll
    for (int i = jj; i < 1024; i += 128) hb0[i] = 0.0f;

    float wreg[NREG][4];
    #pragma unroll
    for (int i = 0; i < NREG; i++)
        #pragma unroll
        for (int gx = 0; gx < 4; gx++)
            wreg[i][gx] = whhTs[(size_t)(RES + i) * G4 + jj + gx * 128];

    float c[8];
    #pragma unroll
    for (int q = 0; q < 8; q++) c[q] = 0.0f;

    const float* xp = d_xproj + (size_t)(s * 4 + bg) * Tv * (G4 * 8);
    u64t xc[16];
    #pragma unroll
    for (int gx = 0; gx < 4; gx++) {
        const ulonglong2* p =
            reinterpret_cast<const ulonglong2*>(xp + (size_t)(jj + gx * 128) * 8);
        ulonglong2 v0 = p[0], v1 = p[1];
        xc[gx * 4 + 0] = v0.x; xc[gx * 4 + 1] = v0.y;
        xc[gx * 4 + 2] = v1.x; xc[gx * 4 + 3] = v1.y;
    }

    float* hcur = hb0;
    float* hnxt = hb1;
    __syncthreads();

    for (int t = 0; t < Tv; t++) {
        u64t acc[16];
        #pragma unroll
        for (int q = 0; q < 16; q++) acc[q] = xc[q];
        if (t < Tv - 1) {
            const float* xn = xp + (size_t)(t + 1) * (G4 * 8);
            #pragma unroll
            for (int gx = 0; gx < 4; gx++) {
                const ulonglong2* p =
                    reinterpret_cast<const ulonglong2*>(xn + (size_t)(jj + gx * 128) * 8);
                ulonglong2 v0 = p[0], v1 = p[1];
                xc[gx * 4 + 0] = v0.x; xc[gx * 4 + 1] = v0.y;
                xc[gx * 4 + 2] = v1.x; xc[gx * 4 + 3] = v1.y;
            }
        }

        #pragma unroll 2
        for (int k = 0; k < RES; k++) {
            const float* wr = &wlo[k * G4 + jj];
            float w0 = wr[0], w1 = wr[128], w2 = wr[256], w3 = wr[384];
            const ulonglong2* hp = reinterpret_cast<const ulonglong2*>(&hcur[k * 8]);
            ulonglong2 h0 = hp[0], h1 = hp[1];
            u64t W;
            W = pk2(w0, w0);
            acc[0]  = fma2(h0.x, W, acc[0]);  acc[1]  = fma2(h0.y, W, acc[1]);
            acc[2]  = fma2(h1.x, W, acc[2]);  acc[3]  = fma2(h1.y, W, acc[3]);
            W = pk2(w1, w1);
            acc[4]  = fma2(h0.x, W, acc[4]);  acc[5]  = fma2(h0.y, W, acc[5]);
            acc[6]  = fma2(h1.x, W, acc[6]);  acc[7]  = fma2(h1.y, W, acc[7]);
            W = pk2(w2, w2);
            acc[8]  = fma2(h0.x, W, acc[8]);  acc[9]  = fma2(h0.y, W, acc[9]);
            acc[10] = fma2(h1.x, W, acc[10]); acc[11] = fma2(h1.y, W, acc[11]);
            W = pk2(w3, w3);
            acc[12] = fma2(h0.x, W, acc[12]); acc[13] = fma2(h0.y, W, acc[13]);
            acc[14] = fma2(h1.x, W, acc[14]); acc[15] = fma2(h1.y, W, acc[15]);
        }
        #pragma unroll
        for (int i = 0; i < NREG; i++) {
            int k = RES + i;
            const ulonglong2* hp = reinterpret_cast<const ulonglong2*>(&hcur[k * 8]);
            ulonglong2 h0 = hp[0], h1 = hp[1];
            u64t W;
            W = pk2(wreg[i][0], wreg[i][0]);
            acc[0]  = fma2(h0.x, W, acc[0]);  acc[1]  = fma2(h0.y, W, acc[1]);
            acc[2]  = fma2(h1.x, W, acc[2]);  acc[3]  = fma2(h1.y, W, acc[3]);
            W = pk2(wreg[i][1], wreg[i][1]);
            acc[4]  = fma2(h0.x, W, acc[4]);  acc[5]  = fma2(h0.y, W, acc[5]);
            acc[6]  = fma2(h1.x, W, acc[6]);  acc[7]  = fma2(h1.y, W, acc[7]);
            W = pk2(wreg[i][2], wreg[i][2]);
            acc[8]  = fma2(h0.x, W, acc[8]);  acc[9]  = fma2(h0.y, W, acc[9]);
            acc[10] = fma2(h1.x, W, acc[10]); acc[11] = fma2(h1.y, W, acc[11]);
            W = pk2(wreg[i][3], wreg[i][3]);
            acc[12] = fma2(h0.x, W, acc[12]); acc[13] = fma2(h0.y, W, acc[13]);
            acc[14] = fma2(h1.x, W, acc[14]); acc[15] = fma2(h1.y, W, acc[15]);
        }

        // wait: all threads done reading hcur before hnxt writes? hnxt != hcur,
        // but hnxt was hcur two steps ago; its readers finished last step (sync).
        // Thread-local gate update: acc[0..3]=i, [4..7]=f, [8..11]=g, [12..15]=o
        u64t hu[4];
        #pragma unroll
        for (int p = 0; p < 4; p++) {
            float2 iv = up2(acc[p]),      fv = up2(acc[4 + p]);
            float2 gv = up2(acc[8 + p]),  ov = up2(acc[12 + p]);
            c[2 * p]     = sigf(fv.x) * c[2 * p]     + sigf(iv.x) * tanhfast(gv.x);
            c[2 * p + 1] = sigf(fv.y) * c[2 * p + 1] + sigf(iv.y) * tanhfast(gv.y);
            float h0v = sigf(ov.x) * tanhfast(c[2 * p]);
            float h1v = sigf(ov.y) * tanhfast(c[2 * p + 1]);
            hu[p] = pk2(h0v, h1v);
        }
        {
            ulonglong2 s0; s0.x = hu[0]; s0.y = hu[1];
            ulonglong2 s1; s1.x = hu[2]; s1.y = hu[3];
            reinterpret_cast<ulonglong2*>(&hnxt[jj * 8])[0] = s0;
            reinterpret_cast<ulonglong2*>(&hnxt[jj * 8])[1] = s1;
        }
        __syncthreads();
        float* tmp = hcur; hcur = hnxt; hnxt = tmp;
    }

    // final h for unit n=jj is this thread's last write (now in hcur)
    #pragma unroll
    for (int bi = 0; bi < 8; bi++)
        d_hfin[((size_t)s * Bv + (bg * 8 + bi)) * HLv + jj] = hcur[jj * 8 + bi];
}

// =====================================================================
// kD: final linear + lrelu
// =====================================================================
__global__ void kD(const float* __restrict__ wlin, const float* __restrict__ blin,
                   float* __restrict__ out) {
    int s = blockIdx.x >> 5, b = blockIdx.x & 31;
    int f = threadIdx.x;
    __shared__ float hs[HLv];
    for (int i = threadIdx.x; i < HLv; i += 32)
        hs[i] = d_hfin[((size_t)s * Bv + b) * HLv + i];
    __syncthreads();
    if (f < FUT) {
        float a = blin[f];
        #pragma unroll 8
        for (int k = 0; k < HLv; k++) a += hs[k] * wlin[f * HLv + k];
        out[((size_t)b * NHv + s) * FUT + f] = lrelu(a);
    }
}

// =====================================================================
extern "C" void kernel_launch(void* const* d_in, const int* in_sizes, int n_in,
                              void* d_out, int out_size) {
    const float* meteo = (const float*)d_in[0];
    const float* hydro = (const float*)d_in[1];
    if (in_sizes[0] == Bv * Tv * NHv) {
        hydro = (const float*)d_in[0];
        meteo = (const float*)d_in[1];
    }
    const void*  ei    = d_in[2];
    const float* Wr    = (const float*)d_in[3];
    const float* Wl    = (const float*)d_in[4];
    const float* bgnn  = (const float*)d_in[5];
    const float* Wih   = (const float*)d_in[6];
    const float* Whh   = (const float*)d_in[7];
    if (in_sizes[6] == NHv * G4 * HLv) {
        Whh = (const float*)d_in[6];
        Wih = (const float*)d_in[7];
    }
    const float* bih   = (const float*)d_in[8];
    const float* bhh   = (const float*)d_in[9];
    const float* Wlin  = (const float*)d_in[10];
    const float* blin  = (const float*)d_in[11];
    float* out = (float*)d_out;

    cudaFuncSetAttribute(kC, cudaFuncAttributeMaxDynamicSharedMemorySize, SMEM_C);

    kE<<<1, 256>>>(ei);
    kA<<<GT, 128>>>(hydro, meteo, Wr, Wl, bgnn);
    kT<<<dim3(4, 16, NHv), dim3(32, 8)>>>(Whh, G4, HLv, 0);
    kT<<<dim3(2, 16, NHv), dim3(32, 8)>>>(Wih, G4, HGv, 1);
    kBias<<<NHv, 512>>>(bih, bhh);
    kB<<<dim3(Tv, NHv, 2), 128>>>();
    kC<<<128, 128, SMEM_C>>>();
    kD<<<NHv * Bv, 32>>>(Wlin, blin, out);
}

// round 8
// speedup vs baseline: 1.8389x; 1.1466x over previous
#include <cuda_runtime.h>
#include <cstdint>

#define Bv   32
#define Tv   168
#define NHv  32
#define NMv  64
#define Ev   384
#define HGv  64
#define HLv  128
#define G4   512
#define FUT  24
#define GT   (Bv*Tv)

#define RES   104        // Whh rows resident in smem (kC)
#define NREG  24         // Whh rows resident in registers (kC)

// -------- scratch --------
__device__ float d_gnnh[(size_t)NHv * Tv * Bv * HGv];     // [s][t][b][k]
__device__ float d_whhT[(size_t)NHv * HLv * G4];          // [s][k][j]
__device__ float d_wihT[(size_t)NHv * HGv * G4];          // [s][k][j]
__device__ float d_bsum[NHv * G4];
__device__ float d_xproj[(size_t)NHv * 4 * Tv * G4 * 8];  // [(s*4+bg)][t][j][bi]
__device__ float d_hfin[NHv * Bv * HLv];                  // [s][b][n]
__device__ int   d_edges[2 * Ev];

typedef unsigned long long u64t;

__device__ __forceinline__ u64t pk2(float x, float y) {
    u64t r; asm("mov.b64 %0,{%1,%2};" : "=l"(r) : "f"(x), "f"(y)); return r;
}
__device__ __forceinline__ float2 up2(u64t v) {
    float2 f; asm("mov.b64 {%0,%1},%2;" : "=f"(f.x), "=f"(f.y) : "l"(v)); return f;
}
__device__ __forceinline__ u64t fma2(u64t a, u64t b, u64t c) {
    u64t r; asm("fma.rn.f32x2 %0,%1,%2,%3;" : "=l"(r) : "l"(a), "l"(b), "l"(c)); return r;
}
__device__ __forceinline__ float sigf(float x) {
    return __fdividef(1.0f, 1.0f + __expf(-x));
}
__device__ __forceinline__ float tanhfast(float x) {
    return 1.0f - 2.0f * __fdividef(1.0f, __expf(2.0f * x) + 1.0f);
}
__device__ __forceinline__ float lrelu(float v) { return v > 0.0f ? v : 0.01f * v; }

// =====================================================================
// kE: dtype-robust edge decode (int64 vs silently-int32 edge_index)
// =====================================================================
__global__ void kE(const void* __restrict__ ei) {
    __shared__ int nz;
    const int* w = (const int*)ei;
    if (threadIdx.x == 0) nz = 0;
    __syncthreads();
    int cnt = 0;
    for (int i = threadIdx.x; i < 2 * Ev; i += blockDim.x)
        if ((i & 1) && w[i] == 0) cnt++;
    for (int o = 16; o > 0; o >>= 1) cnt += __shfl_down_sync(0xffffffffu, cnt, o);
    if ((threadIdx.x & 31) == 0) atomicAdd(&nz, cnt);
    __syncthreads();
    bool is64 = (nz > 100);
    for (int i = threadIdx.x; i < 2 * Ev; i += blockDim.x)
        d_edges[i] = is64 ? (int)((const long long*)ei)[i] : w[i];
}

// =====================================================================
// kA: GNN per graph g = b*Tv + t. Output [s][t][b][k]. smem atomics for agg.
// =====================================================================
__global__ void __launch_bounds__(128) kA(
        const float* __restrict__ hyd, const float* __restrict__ met,
        const float* __restrict__ Wr, const float* __restrict__ Wl,
        const float* __restrict__ bg) {
    __shared__ float xv[96], agg[NHv], wr[HGv], wl[HGv], bb[HGv];
    int g = blockIdx.x;
    int t = g % Tv, b = g / Tv;
    int tid = threadIdx.x;

    if (tid < NHv) { xv[tid] = hyd[(size_t)g * NHv + tid]; agg[tid] = 0.0f; }
    if (tid >= 32 && tid < 96) xv[tid] = met[(size_t)g * NMv + (tid - 32)];
    if (tid < HGv) { wr[tid] = Wr[tid]; wl[tid] = Wl[tid]; bb[tid] = bg[tid]; }
    __syncthreads();

    #pragma unroll
    for (int r = 0; r < 3; r++) {
        int e = tid + r * 128;
        int dn = d_edges[Ev + e];
        if (dn < NHv) atomicAdd(&agg[dn], xv[d_edges[e]]);
    }
    __syncthreads();

    #pragma unroll
    for (int i = 0; i < 16; i++) {
        int idx = tid + i * 128;
        int s = idx >> 6, k = idx & 63;
        float v = xv[s] * wr[k] + agg[s] * wl[k] + bb[k];
        d_gnnh[(((size_t)s * Tv + t) * Bv + b) * HGv + k] = lrelu(v);
    }
}

// =====================================================================
// kT: tiled per-station transpose [s][J][K] -> [s][K][J]. which: 0=whh,1=wih
// =====================================================================
__global__ void kT(const float* __restrict__ src, int J, int K, int which) {
    __shared__ float tile[32][33];
    int s = blockIdx.z;
    int k0 = blockIdx.x * 32, j0 = blockIdx.y * 32;
    int tx = threadIdx.x, ty = threadIdx.y;
    const float* S = src + (size_t)s * J * K;
    float* D = (which == 0 ? d_whhT : d_wihT) + (size_t)s * J * K;
    #pragma unroll
    for (int dy = 0; dy < 32; dy += 8)
        tile[ty + dy][tx] = S[(size_t)(j0 + ty + dy) * K + (k0 + tx)];
    __syncthreads();
    #pragma unroll
    for (int dy = 0; dy < 32; dy += 8)
        D[(size_t)(k0 + ty + dy) * J + (j0 + tx)] = tile[tx][ty + dy];
}

__global__ void kBias(const float* __restrict__ bih, const float* __restrict__ bhh) {
    int s = blockIdx.x, j = threadIdx.x;
    d_bsum[s * G4 + j] = bih[s * G4 + j] + bhh[s * G4 + j];
}

// =====================================================================
// kB: input projection. grid (t, s, z), 128 threads; thread jj: 4 j's, 16 b.
// =====================================================================
__global__ void __launch_bounds__(128) kB() {
    int t = blockIdx.x, s = blockIdx.y, z = blockIdx.z;
    int jj = threadIdx.x;
    int j0 = jj * 4;
    __shared__ float hloc[64 * 20];  // [k][b16], pad to 20

    {
        const float* src = &d_gnnh[(((size_t)s * Tv + t) * Bv + z * 16) * HGv];
        #pragma unroll
        for (int r = 0; r < 2; r++) {
            int id = jj + r * 128;
            float4 v = reinterpret_cast<const float4*>(src)[id];
            int b = id >> 4, k0 = (id & 15) * 4;
            hloc[(k0 + 0) * 20 + b] = v.x;
            hloc[(k0 + 1) * 20 + b] = v.y;
            hloc[(k0 + 2) * 20 + b] = v.z;
            hloc[(k0 + 3) * 20 + b] = v.w;
        }
    }
    __syncthreads();

    u64t acc[4][8];
    {
        float4 bb = *reinterpret_cast<const float4*>(&d_bsum[s * G4 + j0]);
        float bv[4] = {bb.x, bb.y, bb.z, bb.w};
        #pragma unroll
        for (int jl = 0; jl < 4; jl++) {
            u64t b2 = pk2(bv[jl], bv[jl]);
            #pragma unroll
            for (int q = 0; q < 8; q++) acc[jl][q] = b2;
        }
    }

    const float* wT = d_wihT + (size_t)s * (HGv * G4);
    #pragma unroll 2
    for (int k = 0; k < 64; k++) {
        float4 w = *reinterpret_cast<const float4*>(&wT[k * G4 + j0]);
        float wv[4] = {w.x, w.y, w.z, w.w};
        const ulonglong2* hp = reinterpret_cast<const ulonglong2*>(&hloc[k * 20]);
        ulonglong2 h0 = hp[0], h1 = hp[1], h2 = hp[2], h3 = hp[3];
        #pragma unroll
        for (int jl = 0; jl < 4; jl++) {
            u64t W = pk2(wv[jl], wv[jl]);
            acc[jl][0] = fma2(h0.x, W, acc[jl][0]);
            acc[jl][1] = fma2(h0.y, W, acc[jl][1]);
            acc[jl][2] = fma2(h1.x, W, acc[jl][2]);
            acc[jl][3] = fma2(h1.y, W, acc[jl][3]);
            acc[jl][4] = fma2(h2.x, W, acc[jl][4]);
            acc[jl][5] = fma2(h2.y, W, acc[jl][5]);
            acc[jl][6] = fma2(h3.x, W, acc[jl][6]);
            acc[jl][7] = fma2(h3.y, W, acc[jl][7]);
        }
    }

    #pragma unroll
    for (int jl = 0; jl < 4; jl++) {
        #pragma unroll
        for (int half = 0; half < 2; half++) {
            float* base = &d_xproj[(((size_t)(s * 4 + z * 2 + half) * Tv + t) * G4
                                    + (j0 + jl)) * 8];
            ulonglong2 v0, v1;
            v0.x = acc[jl][half * 4 + 0]; v0.y = acc[jl][half * 4 + 1];
            v1.x = acc[jl][half * 4 + 2]; v1.y = acc[jl][half * 4 + 3];
            reinterpret_cast<ulonglong2*>(base)[0] = v0;
            reinterpret_cast<ulonglong2*>(base)[1] = v1;
        }
    }
}

// =====================================================================
// kC: recurrence. 128 blocks = (s, bg), 256 threads (2 warps/SMSP).
// Thread = (unit n = tid&127, batch-half bh = tid>>7). Owns gates
// {n, n+128, n+256, n+384} x 4 batches -> thread-local gate update.
// Weights packed wpk[k][n][4] -> one LDS.128 per k. RES rows smem, NREG regs.
// =====================================================================
#define SMEM_C (RES * G4 * 4 + 2 * 1024 * 4)

extern __shared__ float smc[];

__global__ void __launch_bounds__(256) kC() {
    int blk = blockIdx.x;
    int s = blk >> 2, bg = blk & 3;
    int tid = threadIdx.x;
    int n = tid & 127;       // hidden unit
    int bh = tid >> 7;       // batch half: batches bh*4 .. bh*4+3

    float* wpk = smc;                   // [RES][128n][4g] packed
    float* hb0 = smc + RES * G4;        // [128n][8bi] double buffer
    float* hb1 = hb0 + 1024;

    const float* whhTs = d_whhT + (size_t)s * (HLv * G4);
    // pack: wpk[k*512 + nn*4 + g] = whhT[k][g*128 + nn]
    for (int i = tid; i < RES * G4; i += 256) {
        int k = i >> 9, q = i & 511;
        int nn = q >> 2, g = q & 3;
        wpk[i] = whhTs[(size_t)k * G4 + g * 128 + nn];
    }
    for (int i = tid; i < 1024; i += 256) hb0[i] = 0.0f;

    float wreg[NREG][4];
    #pragma unroll
    for (int r = 0; r < NREG; r++)
        #pragma unroll
        for (int g = 0; g < 4; g++)
            wreg[r][g] = whhTs[(size_t)(RES + r) * G4 + g * 128 + n];

    float c[4];
    #pragma unroll
    for (int q = 0; q < 4; q++) c[q] = 0.0f;

    const float* xp = d_xproj + (size_t)(s * 4 + bg) * Tv * (G4 * 8);
    float4 xc[4];
    #pragma unroll
    for (int g = 0; g < 4; g++)
        xc[g] = *reinterpret_cast<const float4*>(xp + (size_t)(n + g * 128) * 8 + bh * 4);

    float* hcur = hb0;
    float* hnxt = hb1;
    __syncthreads();

    for (int t = 0; t < Tv; t++) {
        u64t acc[8];
        #pragma unroll
        for (int g = 0; g < 4; g++) {
            acc[2 * g + 0] = pk2(xc[g].x, xc[g].y);
            acc[2 * g + 1] = pk2(xc[g].z, xc[g].w);
        }
        if (t < Tv - 1) {
            const float* xn = xp + (size_t)(t + 1) * (G4 * 8);
            #pragma unroll
            for (int g = 0; g < 4; g++)
                xc[g] = *reinterpret_cast<const float4*>(
                    xn + (size_t)(n + g * 128) * 8 + bh * 4);
        }

        #pragma unroll 4
        for (int k = 0; k < RES; k++) {
            float4 w = *reinterpret_cast<const float4*>(&wpk[k * G4 + n * 4]);
            ulonglong2 h = *reinterpret_cast<const ulonglong2*>(&hcur[k * 8 + bh * 4]);
            u64t W;
            W = pk2(w.x, w.x);
            acc[0] = fma2(h.x, W, acc[0]); acc[1] = fma2(h.y, W, acc[1]);
            W = pk2(w.y, w.y);
            acc[2] = fma2(h.x, W, acc[2]); acc[3] = fma2(h.y, W, acc[3]);
            W = pk2(w.z, w.z);
            acc[4] = fma2(h.x, W, acc[4]); acc[5] = fma2(h.y, W, acc[5]);
            W = pk2(w.w, w.w);
            acc[6] = fma2(h.x, W, acc[6]); acc[7] = fma2(h.y, W, acc[7]);
        }
        #pragma unroll
        for (int r = 0; r < NREG; r++) {
            int k = RES + r;
            ulonglong2 h = *reinterpret_cast<const ulonglong2*>(&hcur[k * 8 + bh * 4]);
            u64t W;
            W = pk2(wreg[r][0], wreg[r][0]);
            acc[0] = fma2(h.x, W, acc[0]); acc[1] = fma2(h.y, W, acc[1]);
            W = pk2(wreg[r][1], wreg[r][1]);
            acc[2] = fma2(h.x, W, acc[2]); acc[3] = fma2(h.y, W, acc[3]);
            W = pk2(wreg[r][2], wreg[r][2]);
            acc[4] = fma2(h.x, W, acc[4]); acc[5] = fma2(h.y, W, acc[5]);
            W = pk2(wreg[r][3], wreg[r][3]);
            acc[6] = fma2(h.x, W, acc[6]); acc[7] = fma2(h.y, W, acc[7]);
        }

        // thread-local gate update: acc[0,1]=i, [2,3]=f, [4,5]=g, [6,7]=o
        {
            float2 i0 = up2(acc[0]), i1 = up2(acc[1]);
            float2 f0 = up2(acc[2]), f1 = up2(acc[3]);
            float2 g0 = up2(acc[4]), g1 = up2(acc[5]);
            float2 o0 = up2(acc[6]), o1 = up2(acc[7]);
            float4 hv;
            c[0] = sigf(f0.x) * c[0] + sigf(i0.x) * tanhfast(g0.x);
            hv.x = sigf(o0.x) * tanhfast(c[0]);
            c[1] = sigf(f0.y) * c[1] + sigf(i0.y) * tanhfast(g0.y);
            hv.y = sigf(o0.y) * tanhfast(c[1]);
            c[2] = sigf(f1.x) * c[2] + sigf(i1.x) * tanhfast(g1.x);
            hv.z = sigf(o1.x) * tanhfast(c[2]);
            c[3] = sigf(f1.y) * c[3] + sigf(i1.y) * tanhfast(g1.y);
            hv.w = sigf(o1.y) * tanhfast(c[3]);
            *reinterpret_cast<float4*>(&hnxt[n * 8 + bh * 4]) = hv;
        }
        __syncthreads();
        float* tmp = hcur; hcur = hnxt; hnxt = tmp;
    }

    #pragma unroll
    for (int q = 0; q < 4; q++) {
        int b = bg * 8 + bh * 4 + q;
        d_hfin[((size_t)s * Bv + b) * HLv + n] = hcur[n * 8 + bh * 4 + q];
    }
}

// =====================================================================
// kD: final linear + lrelu
// =====================================================================
__global__ void kD(const float* __restrict__ wlin, const float* __restrict__ blin,
                   float* __restrict__ out) {
    int s = blockIdx.x >> 5, b = blockIdx.x & 31;
    int f = threadIdx.x;
    __shared__ float hs[HLv];
    for (int i = threadIdx.x; i < HLv; i += 32)
        hs[i] = d_hfin[((size_t)s * Bv + b) * HLv + i];
    __syncthreads();
    if (f < FUT) {
        float a = blin[f];
        #pragma unroll 8
        for (int k = 0; k < HLv; k++) a += hs[k] * wlin[f * HLv + k];
        out[((size_t)b * NHv + s) * FUT + f] = lrelu(a);
    }
}

// =====================================================================
extern "C" void kernel_launch(void* const* d_in, const int* in_sizes, int n_in,
                              void* d_out, int out_size) {
    const float* meteo = (const float*)d_in[0];
    const float* hydro = (const float*)d_in[1];
    if (in_sizes[0] == Bv * Tv * NHv) {
        hydro = (const float*)d_in[0];
        meteo = (const float*)d_in[1];
    }
    const void*  ei    = d_in[2];
    const float* Wr    = (const float*)d_in[3];
    const float* Wl    = (const float*)d_in[4];
    const float* bgnn  = (const float*)d_in[5];
    const float* Wih   = (const float*)d_in[6];
    const float* Whh   = (const float*)d_in[7];
    if (in_sizes[6] == NHv * G4 * HLv) {
        Whh = (const float*)d_in[6];
        Wih = (const float*)d_in[7];
    }
    const float* bih   = (const float*)d_in[8];
    const float* bhh   = (const float*)d_in[9];
    const float* Wlin  = (const float*)d_in[10];
    const float* blin  = (const float*)d_in[11];
    float* out = (float*)d_out;

    cudaFuncSetAttribute(kC, cudaFuncAttributeMaxDynamicSharedMemorySize, SMEM_C);

    kE<<<1, 256>>>(ei);
    kA<<<GT, 128>>>(hydro, meteo, Wr, Wl, bgnn);
    kT<<<dim3(4, 16, NHv), dim3(32, 8)>>>(Whh, G4, HLv, 0);
    kT<<<dim3(2, 16, NHv), dim3(32, 8)>>>(Wih, G4, HGv, 1);
    kBias<<<NHv, 512>>>(bih, bhh);
    kB<<<dim3(Tv, NHv, 2), 128>>>();
    kC<<<128, 256, SMEM_C>>>();
    kD<<<NHv * Bv, 32>>>(Wlin, blin, out);
}